// round 12
// baseline (speedup 1.0000x reference)
#include <cuda_runtime.h>
#include <cuda_fp16.h>
#include <cstdint>

#define BB 4
#define TT 4096
#define CC 512
#define HH 64
#define LOG2E 1.4426950408889634f
#define SCALE 0.044194173824159216f   // 512^-0.5
#define CH 8                           // k-tiles (64 keys) per split-K chunk

// fp16 operands
__device__ __half g_qh[BB * TT * HH];      // q * SCALE * log2e, [tok][h]
__device__ __half g_kh[BB * TT * HH];      // k, [tok][h]
__device__ __half g_vt[BB * HH * TT];      // v transposed, [b][h][t]
__device__ __half g_wh[192 * CC];          // W^T hi, [n][k]
__device__ __half g_wl[192 * CC];          // W^T lo
// split-K partials (fp32); m is in log2 domain
__device__ float g_opart[1024 * 128 * 64];
__device__ float g_mpart[1024 * 128];
__device__ float g_lpart[1024 * 128];

__device__ __forceinline__ uint32_t h2u(__half2 h) {
    union { __half2 h; uint32_t u; } cvt;
    cvt.h = h;
    return cvt.u;
}

__device__ __forceinline__ void mma_f16(float* d, const uint32_t* a,
                                        uint32_t b0, uint32_t b1) {
    asm volatile(
        "mma.sync.aligned.m16n8k16.row.col.f32.f16.f16.f32 "
        "{%0,%1,%2,%3}, {%4,%5,%6,%7}, {%8,%9}, {%0,%1,%2,%3};"
        : "+f"(d[0]), "+f"(d[1]), "+f"(d[2]), "+f"(d[3])
        : "r"(a[0]), "r"(a[1]), "r"(a[2]), "r"(a[3]), "r"(b0), "r"(b1));
}

__device__ __forceinline__ void ldsm4(uint32_t& r0, uint32_t& r1,
                                      uint32_t& r2, uint32_t& r3, uint32_t addr) {
    asm volatile(
        "ldmatrix.sync.aligned.m8n8.x4.shared.b16 {%0,%1,%2,%3}, [%4];"
        : "=r"(r0), "=r"(r1), "=r"(r2), "=r"(r3) : "r"(addr));
}

__device__ __forceinline__ void cp16(uint32_t dst, const void* src) {
    asm volatile("cp.async.cg.shared.global [%0], [%1], 16;"
                 :: "r"(dst), "l"(src) : "memory");
}
#define CP_COMMIT() asm volatile("cp.async.commit_group;" ::: "memory")
#define CP_WAIT1() asm volatile("cp.async.wait_group 1;" ::: "memory")
#define CP_WAIT0() asm volatile("cp.async.wait_group 0;" ::: "memory")

// ---------------------------------------------------------------------------
// W transpose + fp16 hi/lo split
// ---------------------------------------------------------------------------
__global__ __launch_bounds__(256) void wsplit_kernel(
    const float* __restrict__ Wk,
    const float* __restrict__ Wq,
    const float* __restrict__ Wv)
{
    int idx = blockIdx.x * 256 + threadIdx.x;   // 384 x 256 = 98304 = 192*512
    int k = idx / 192, n = idx - k * 192;
    const float* W = (n < 64) ? Wk : (n < 128) ? Wq : Wv;
    float w = W[k * HH + (n & 63)];
    __half hi = __float2half_rn(w);
    g_wh[n * CC + k] = hi;
    g_wl[n * CC + k] = __float2half_rn(w - __half2float(hi));
}

// ---------------------------------------------------------------------------
// Projection: fp16 2-term (xh*wh + xh*wl), m16n8k16, fp32 accum.
// x staged fp32 via cp.async, rounded to fp16 in registers.
// CTA 256 thr (8 warps): tile M=64 x N=192, K-chunk 32, double-buffer, grid 256.
// Warp (mw = w>>2 in 0..1, nw = w&3): 32x48 warp tile (2 mf x 6 nf).
// ---------------------------------------------------------------------------
#define PXB(buf) ((buf) * 9216)
#define PWB(buf) (18432 + (buf) * 30720)
#define PWLO 15360
#define PSMEM 79872

__global__ __launch_bounds__(256) void proj_mma(const float* __restrict__ x)
{
    extern __shared__ char smp[];
    uint32_t sbase;
    asm("{ .reg .u64 t; cvta.to.shared.u64 t, %1; cvt.u32.u64 %0, t; }"
        : "=r"(sbase) : "l"(smp));

    const int tid = threadIdx.x;
    const int w = tid >> 5;
    const int lane = tid & 31;
    const int r = lane >> 2;
    const int c = lane & 3;
    const int mw = w >> 2, nw = w & 3;
    const int row0 = blockIdx.x * 64;

    float acc[2][6][4];
#pragma unroll
    for (int mf = 0; mf < 2; mf++)
#pragma unroll
        for (int nf = 0; nf < 6; nf++)
#pragma unroll
            for (int j = 0; j < 4; j++) acc[mf][nf][j] = 0.f;

    auto issue = [&](int ck, int buf) {
        const int k0 = ck * 32;
        for (int t = tid; t < 512; t += 256) {        // X fp32: 64 rows x 8 segs
            int rr = t >> 3, seg = t & 7;
            cp16(sbase + PXB(buf) + rr * 144 + seg * 16,
                 &x[(size_t)(row0 + rr) * CC + k0 + seg * 4]);
        }
        for (int t = tid; t < 768; t += 256) {        // W hi+lo: 192 rows x 4 segs
            int n = t >> 2, seg = t & 3;
            cp16(sbase + PWB(buf) + n * 80 + seg * 16,
                 &g_wh[n * CC + k0 + seg * 8]);
            cp16(sbase + PWB(buf) + PWLO + n * 80 + seg * 16,
                 &g_wl[n * CC + k0 + seg * 8]);
        }
    };

    issue(0, 0);
    CP_COMMIT();

    for (int ck = 0; ck < 16; ck++) {
        const int buf = ck & 1;
        if (ck + 1 < 16) {
            issue(ck + 1, buf ^ 1);
            CP_COMMIT();
            CP_WAIT1();
        } else {
            CP_WAIT0();
        }
        __syncthreads();

        const float* Xf = (const float*)(smp + PXB(buf));
        const uint32_t* Wh32 = (const uint32_t*)(smp + PWB(buf));
        const uint32_t* Wl32 = (const uint32_t*)(smp + PWB(buf) + PWLO);

#pragma unroll
        for (int kk = 0; kk < 2; kk++) {
            uint32_t ah[2][4];
#pragma unroll
            for (int mf = 0; mf < 2; mf++) {
                int rb = 32 * mw + 16 * mf;
                const float* p0 = &Xf[(rb + r) * 36 + kk * 16 + 2 * c];
                const float* p1 = &Xf[(rb + 8 + r) * 36 + kk * 16 + 2 * c];
                float2 v0 = *(const float2*)p0;
                float2 v1 = *(const float2*)p1;
                float2 v2 = *(const float2*)(p0 + 8);
                float2 v3 = *(const float2*)(p1 + 8);
                ah[mf][0] = h2u(__floats2half2_rn(v0.x, v0.y));
                ah[mf][1] = h2u(__floats2half2_rn(v1.x, v1.y));
                ah[mf][2] = h2u(__floats2half2_rn(v2.x, v2.y));
                ah[mf][3] = h2u(__floats2half2_rn(v3.x, v3.y));
            }
#pragma unroll
            for (int nf = 0; nf < 6; nf++) {
                int bi = (48 * nw + 8 * nf + r) * 20 + kk * 8 + c;
                uint32_t bh0 = Wh32[bi], bh1 = Wh32[bi + 4];
                uint32_t bl0 = Wl32[bi], bl1 = Wl32[bi + 4];
#pragma unroll
                for (int mf = 0; mf < 2; mf++) {
                    mma_f16(acc[mf][nf], ah[mf], bh0, bh1);
                    mma_f16(acc[mf][nf], ah[mf], bl0, bl1);
                }
            }
        }
        __syncthreads();
    }

    // epilogue: n<64 -> k, 64..127 -> q (scaled into log2 domain), 128..191 -> v^T
    const float qs = SCALE * LOG2E;
#pragma unroll
    for (int mf = 0; mf < 2; mf++) {
#pragma unroll
        for (int nf = 0; nf < 6; nf++) {
            int n = 48 * nw + 8 * nf + 2 * c;
            int r0 = row0 + 32 * mw + 16 * mf + r;
            float v0 = acc[mf][nf][0], v1 = acc[mf][nf][1];
            float v2 = acc[mf][nf][2], v3 = acc[mf][nf][3];
            if (n < 64) {
                *(__half2*)&g_kh[(size_t)r0 * HH + n] = __floats2half2_rn(v0, v1);
                *(__half2*)&g_kh[(size_t)(r0 + 8) * HH + n] = __floats2half2_rn(v2, v3);
            } else if (n < 128) {
                *(__half2*)&g_qh[(size_t)r0 * HH + n - 64] =
                    __floats2half2_rn(v0 * qs, v1 * qs);
                *(__half2*)&g_qh[(size_t)(r0 + 8) * HH + n - 64] =
                    __floats2half2_rn(v2 * qs, v3 * qs);
            } else {
                int hh = n - 128;
                int b = r0 >> 12, t = r0 & 4095;
                size_t vb = (size_t)b * HH * TT;
                g_vt[vb + (size_t)hh * TT + t]       = __float2half_rn(v0);
                g_vt[vb + (size_t)(hh + 1) * TT + t] = __float2half_rn(v1);
                g_vt[vb + (size_t)hh * TT + t + 8]       = __float2half_rn(v2);
                g_vt[vb + (size_t)(hh + 1) * TT + t + 8] = __float2half_rn(v3);
            }
        }
    }
}

// ---------------------------------------------------------------------------
// Split-K flash attention partial, fp16 m16n8k16, ldmatrix + cp.async pipe.
// Softmax in exp2 domain. NO register cap (spills cost more than occupancy).
// CTA = 256 thr (8 warps), Q tile 128 rows; warp w owns rows 16w..16w+15.
// ---------------------------------------------------------------------------
#define QB 0
#define KB 18432
#define KBUF 9216
#define VB 36864
#define ATTN_SMEM 55296

__global__ __launch_bounds__(256) void attn_partial()
{
    const int ch = blockIdx.x, qt = blockIdx.y, b = blockIdx.z;
    const int nkt = 2 * qt + 2;
    if (ch * CH >= nkt) return;

    extern __shared__ __half sma[];
    uint32_t sbase;
    asm("{ .reg .u64 t; cvta.to.shared.u64 t, %1; cvt.u32.u64 %0, t; }"
        : "=r"(sbase) : "l"(sma));

    const int tid = threadIdx.x;
    const int w = tid >> 5;
    const int lane = tid & 31;
    const int r = lane >> 2;
    const int c = lane & 3;
    const int rowA = 16 * w + r;
    const int q0 = qt * 128;
    const size_t base = (size_t)b * TT * HH;
    const size_t vbase = (size_t)b * HH * TT;
    const int unit = (b * 32 + qt) * 8 + ch;

    const uint32_t qa_lane = sbase + QB
        + (16 * w + (lane & 7) + ((lane >> 3) & 1) * 8) * 144
        + ((lane >> 4) & 1) * 16;
    const uint32_t b_lane =
        ((lane & 7) + ((lane >> 4) & 1) * 8) * 144 + ((lane >> 3) & 1) * 16;

    for (int i = tid; i < 128 * 8; i += 256) {
        int row = i >> 3, seg = i & 7;
        *(uint4*)((char*)sma + QB + row * 144 + seg * 16) =
            *(const uint4*)&g_qh[base + (size_t)(q0 + row) * HH + seg * 8];
    }

    const int kt_start = ch * CH;
    const int kt_end = min(kt_start + CH, nkt);

    auto issue = [&](int kt, int buf) {
        const int k0 = kt * 64;
        for (int i = tid; i < 512; i += 256) {
            int row = i >> 3, seg = i & 7;
            cp16(sbase + KB + buf * KBUF + row * 144 + seg * 16,
                 &g_kh[base + (size_t)(k0 + row) * HH + seg * 8]);
            cp16(sbase + VB + buf * KBUF + row * 144 + seg * 16,
                 &g_vt[vbase + (size_t)row * TT + k0 + seg * 8]);
        }
    };

    issue(kt_start, kt_start & 1);
    CP_COMMIT();

    float mA = -1e30f, mB = -1e30f, lA = 0.f, lB = 0.f;
    float o[8][4];
#pragma unroll
    for (int nf = 0; nf < 8; nf++)
#pragma unroll
        for (int j = 0; j < 4; j++) o[nf][j] = 0.f;

    for (int kt = kt_start; kt < kt_end; kt++) {
        const uint32_t kbuf = sbase + KB + (uint32_t)(kt & 1) * KBUF;
        const uint32_t vbuf = sbase + VB + (uint32_t)(kt & 1) * KBUF;
        CP_WAIT0();
        __syncthreads();
        if (kt + 1 < kt_end) {
            issue(kt + 1, (kt + 1) & 1);
            CP_COMMIT();
        }

        // S = Q K^T  (log2-domain logits)
        float s[8][4];
#pragma unroll
        for (int nf = 0; nf < 8; nf++)
#pragma unroll
            for (int j = 0; j < 4; j++) s[nf][j] = 0.f;
#pragma unroll
        for (int kk = 0; kk < 4; kk++) {
            uint32_t a[4];
            ldsm4(a[0], a[1], a[2], a[3], qa_lane + kk * 32);
#pragma unroll
            for (int nfp = 0; nfp < 4; nfp++) {
                uint32_t b0, b1, b2, b3;
                ldsm4(b0, b1, b2, b3,
                      kbuf + b_lane + (uint32_t)(nfp * 2304 + kk * 32));
                mma_f16(s[2 * nfp], a, b0, b1);
                mma_f16(s[2 * nfp + 1], a, b2, b3);
            }
        }

        if (kt >= nkt - 2) {
            int gA = q0 + rowA;
            int k0 = kt * 64;
#pragma unroll
            for (int nf = 0; nf < 8; nf++) {
                int col = k0 + nf * 8 + 2 * c;
                if (col > gA)     s[nf][0] = -1e30f;
                if (col + 1 > gA) s[nf][1] = -1e30f;
                if (col > gA + 8)     s[nf][2] = -1e30f;
                if (col + 1 > gA + 8) s[nf][3] = -1e30f;
            }
        }

        float xA = -1e30f, xB = -1e30f;
#pragma unroll
        for (int nf = 0; nf < 8; nf++) {
            xA = fmaxf(xA, fmaxf(s[nf][0], s[nf][1]));
            xB = fmaxf(xB, fmaxf(s[nf][2], s[nf][3]));
        }
#pragma unroll
        for (int d = 1; d < 4; d <<= 1) {
            xA = fmaxf(xA, __shfl_xor_sync(0xffffffffu, xA, d));
            xB = fmaxf(xB, __shfl_xor_sync(0xffffffffu, xB, d));
        }
        float mnA = fmaxf(mA, xA), mnB = fmaxf(mB, xB);
        float aA = exp2f(mA - mnA), aB = exp2f(mB - mnB);

        uint32_t pp[8][2];
        float sumA = 0.f, sumB = 0.f;
#pragma unroll
        for (int nf = 0; nf < 8; nf++) {
            float p0 = exp2f(s[nf][0] - mnA);
            float p1 = exp2f(s[nf][1] - mnA);
            float p2 = exp2f(s[nf][2] - mnB);
            float p3 = exp2f(s[nf][3] - mnB);
            sumA += p0 + p1;
            sumB += p2 + p3;
            pp[nf][0] = h2u(__floats2half2_rn(p0, p1));
            pp[nf][1] = h2u(__floats2half2_rn(p2, p3));
        }
#pragma unroll
        for (int d = 1; d < 4; d <<= 1) {
            sumA += __shfl_xor_sync(0xffffffffu, sumA, d);
            sumB += __shfl_xor_sync(0xffffffffu, sumB, d);
        }
        lA = lA * aA + sumA;
        lB = lB * aB + sumB;
        mA = mnA;
        mB = mnB;
#pragma unroll
        for (int nf = 0; nf < 8; nf++) {
            o[nf][0] *= aA; o[nf][1] *= aA;
            o[nf][2] *= aB; o[nf][3] *= aB;
        }

        // O += P V
#pragma unroll
        for (int kk = 0; kk < 4; kk++) {
            uint32_t a[4] = { pp[2 * kk][0], pp[2 * kk][1],
                              pp[2 * kk + 1][0], pp[2 * kk + 1][1] };
#pragma unroll
            for (int nfp = 0; nfp < 4; nfp++) {
                uint32_t b0, b1, b2, b3;
                ldsm4(b0, b1, b2, b3,
                      vbuf + b_lane + (uint32_t)(nfp * 2304 + kk * 32));
                mma_f16(o[2 * nfp], a, b0, b1);
                mma_f16(o[2 * nfp + 1], a, b2, b3);
            }
        }
    }

#pragma unroll
    for (int nf = 0; nf < 8; nf++) {
        int colo = nf * 8 + 2 * c;
        *(float2*)&g_opart[(size_t)unit * 8192 + rowA * 64 + colo] =
            make_float2(o[nf][0], o[nf][1]);
        *(float2*)&g_opart[(size_t)unit * 8192 + (rowA + 8) * 64 + colo] =
            make_float2(o[nf][2], o[nf][3]);
    }
    if (c == 0) {
        g_mpart[unit * 128 + rowA] = mA;
        g_mpart[unit * 128 + rowA + 8] = mB;
        g_lpart[unit * 128 + rowA] = lA;
        g_lpart[unit * 128 + rowA + 8] = lB;
    }
}

// ---------------------------------------------------------------------------
// Combine: LSE-merge (log2 domain) up to 8 chunk partials.
// grid (32, BB, 8): z = row eighth. 256 thr: 16 rows x 16 thr, 4 cols each...
// Layout: row = rz*16 + tid>>4, col = (tid&15)*4.
// ---------------------------------------------------------------------------
__global__ __launch_bounds__(256) void attn_combine(float* __restrict__ out)
{
    const int qt = blockIdx.x, b = blockIdx.y, rz = blockIdx.z;
    const int tid = threadIdx.x;
    const int row = rz * 16 + (tid >> 4);
    const int co = (tid & 15) * 4;
    const int nch = (2 * qt + 2 + CH - 1) / CH;
    const int ubase = (b * 32 + qt) * 8;

    float M = -1e30f;
    for (int i = 0; i < nch; i++)
        M = fmaxf(M, g_mpart[(ubase + i) * 128 + row]);

    float L = 0.f;
    float acc[4] = {0.f, 0.f, 0.f, 0.f};

    for (int i = 0; i < nch; i++) {
        float coef = exp2f(g_mpart[(ubase + i) * 128 + row] - M);
        L += coef * g_lpart[(ubase + i) * 128 + row];
        float4 v = *(const float4*)
            &g_opart[(size_t)(ubase + i) * 8192 + row * 64 + co];
        acc[0] += coef * v.x;
        acc[1] += coef * v.y;
        acc[2] += coef * v.z;
        acc[3] += coef * v.w;
    }

    float inv = 1.f / L;
    float4 v = make_float4(acc[0] * inv, acc[1] * inv, acc[2] * inv, acc[3] * inv);
    *(float4*)&out[(size_t)b * TT * HH + (size_t)(qt * 128 + row) * HH + co] = v;
}

// ---------------------------------------------------------------------------
extern "C" void kernel_launch(void* const* d_in, const int* in_sizes, int n_in,
                              void* d_out, int out_size)
{
    const float* x  = (const float*)d_in[0];
    const float* Wk = (const float*)d_in[1];
    const float* Wq = (const float*)d_in[2];
    const float* Wv = (const float*)d_in[3];
    float* out = (float*)d_out;

    cudaFuncSetAttribute(proj_mma, cudaFuncAttributeMaxDynamicSharedMemorySize, PSMEM);
    cudaFuncSetAttribute(attn_partial, cudaFuncAttributeMaxDynamicSharedMemorySize, ATTN_SMEM);

    wsplit_kernel<<<384, 256>>>(Wk, Wq, Wv);
    proj_mma<<<256, 256, PSMEM>>>(x);
    attn_partial<<<dim3(8, 32, BB), 256, ATTN_SMEM>>>();
    attn_combine<<<dim3(32, BB, 8), 256>>>(out);
}

// round 14
// speedup vs baseline: 1.4491x; 1.4491x over previous
#include <cuda_runtime.h>
#include <cuda_fp16.h>
#include <cstdint>

#define BB 4
#define TT 4096
#define CC 512
#define HH 64
#define LOG2E 1.4426950408889634f
#define SCALE 0.044194173824159216f   // 512^-0.5
#define CH 8                           // k-tiles (64 keys) per split-K chunk

// fp16 operands
__device__ __half g_qh[BB * TT * HH];      // q * SCALE * log2e, [tok][h]
__device__ __half g_kh[BB * TT * HH];      // k, [tok][h]
__device__ __half g_vt[BB * HH * TT];      // v transposed, [b][h][t]
__device__ __half g_wh[192 * CC];          // W^T hi, [n][k]
__device__ __half g_wl[192 * CC];          // W^T lo
// split-K partials; O in fp16 (halves combine DRAM traffic), m/l fp32 (log2 domain)
__device__ __half g_opart[1024 * 128 * 64];
__device__ float g_mpart[1024 * 128];
__device__ float g_lpart[1024 * 128];

__device__ __forceinline__ uint32_t h2u(__half2 h) {
    union { __half2 h; uint32_t u; } cvt;
    cvt.h = h;
    return cvt.u;
}

// fp32 pair -> fp16 hi + fp16 lo (packed)
__device__ __forceinline__ void split2(float2 v, uint32_t& hi, uint32_t& lo) {
    __half2 h = __floats2half2_rn(v.x, v.y);
    float2 hf = __half22float2(h);
    lo = h2u(__floats2half2_rn(v.x - hf.x, v.y - hf.y));
    hi = h2u(h);
}

__device__ __forceinline__ void mma_f16(float* d, const uint32_t* a,
                                        uint32_t b0, uint32_t b1) {
    asm volatile(
        "mma.sync.aligned.m16n8k16.row.col.f32.f16.f16.f32 "
        "{%0,%1,%2,%3}, {%4,%5,%6,%7}, {%8,%9}, {%0,%1,%2,%3};"
        : "+f"(d[0]), "+f"(d[1]), "+f"(d[2]), "+f"(d[3])
        : "r"(a[0]), "r"(a[1]), "r"(a[2]), "r"(a[3]), "r"(b0), "r"(b1));
}

__device__ __forceinline__ void ldsm4(uint32_t& r0, uint32_t& r1,
                                      uint32_t& r2, uint32_t& r3, uint32_t addr) {
    asm volatile(
        "ldmatrix.sync.aligned.m8n8.x4.shared.b16 {%0,%1,%2,%3}, [%4];"
        : "=r"(r0), "=r"(r1), "=r"(r2), "=r"(r3) : "r"(addr));
}

__device__ __forceinline__ void cp16(uint32_t dst, const void* src) {
    asm volatile("cp.async.cg.shared.global [%0], [%1], 16;"
                 :: "r"(dst), "l"(src) : "memory");
}
#define CP_COMMIT() asm volatile("cp.async.commit_group;" ::: "memory")
#define CP_WAIT1() asm volatile("cp.async.wait_group 1;" ::: "memory")
#define CP_WAIT0() asm volatile("cp.async.wait_group 0;" ::: "memory")

// ---------------------------------------------------------------------------
// W transpose + fp16 hi/lo split
// ---------------------------------------------------------------------------
__global__ __launch_bounds__(256) void wsplit_kernel(
    const float* __restrict__ Wk,
    const float* __restrict__ Wq,
    const float* __restrict__ Wv)
{
    int idx = blockIdx.x * 256 + threadIdx.x;   // 384 x 256 = 98304 = 192*512
    int k = idx / 192, n = idx - k * 192;
    const float* W = (n < 64) ? Wk : (n < 128) ? Wq : Wv;
    float w = W[k * HH + (n & 63)];
    __half hi = __float2half_rn(w);
    g_wh[n * CC + k] = hi;
    g_wl[n * CC + k] = __float2half_rn(w - __half2float(hi));
}

// ---------------------------------------------------------------------------
// Projection: fp16 3-term (xh*wh + xh*wl + xl*wh), m16n8k16, fp32 accum.
// x staged fp32 via cp.async, split to hi/lo fp16 in registers (R10 config).
// CTA 256 thr (8 warps): tile M=128 x N=192, K-chunk 32, double-buffer, grid 128.
// ---------------------------------------------------------------------------
#define PXB(buf) ((buf) * 18432)
#define PWB(buf) (36864 + (buf) * 30720)
#define PWLO 15360
#define PSMEM 98304

__global__ __launch_bounds__(256) void proj_mma(const float* __restrict__ x)
{
    extern __shared__ char smp[];
    uint32_t sbase;
    asm("{ .reg .u64 t; cvta.to.shared.u64 t, %1; cvt.u32.u64 %0, t; }"
        : "=r"(sbase) : "l"(smp));

    const int tid = threadIdx.x;
    const int w = tid >> 5;
    const int lane = tid & 31;
    const int r = lane >> 2;
    const int c = lane & 3;
    const int mw = w >> 2, nw = w & 3;
    const int row0 = blockIdx.x * 128;

    float acc[4][6][4];
#pragma unroll
    for (int mf = 0; mf < 4; mf++)
#pragma unroll
        for (int nf = 0; nf < 6; nf++)
#pragma unroll
            for (int j = 0; j < 4; j++) acc[mf][nf][j] = 0.f;

    auto issue = [&](int ck, int buf) {
        const int k0 = ck * 32;
        for (int t = tid; t < 1024; t += 256) {       // X fp32: 128 rows x 8 segs
            int rr = t >> 3, seg = t & 7;
            cp16(sbase + PXB(buf) + rr * 144 + seg * 16,
                 &x[(size_t)(row0 + rr) * CC + k0 + seg * 4]);
        }
        for (int t = tid; t < 768; t += 256) {        // W hi+lo: 192 rows x 4 segs
            int n = t >> 2, seg = t & 3;
            cp16(sbase + PWB(buf) + n * 80 + seg * 16,
                 &g_wh[n * CC + k0 + seg * 8]);
            cp16(sbase + PWB(buf) + PWLO + n * 80 + seg * 16,
                 &g_wl[n * CC + k0 + seg * 8]);
        }
    };

    issue(0, 0);
    CP_COMMIT();

    for (int ck = 0; ck < 16; ck++) {
        const int buf = ck & 1;
        if (ck + 1 < 16) {
            issue(ck + 1, buf ^ 1);
            CP_COMMIT();
            CP_WAIT1();
        } else {
            CP_WAIT0();
        }
        __syncthreads();

        const float* Xf = (const float*)(smp + PXB(buf));
        const uint32_t* Wh32 = (const uint32_t*)(smp + PWB(buf));
        const uint32_t* Wl32 = (const uint32_t*)(smp + PWB(buf) + PWLO);

#pragma unroll
        for (int kk = 0; kk < 2; kk++) {
            uint32_t ah[4][4], al[4][4];
#pragma unroll
            for (int mf = 0; mf < 4; mf++) {
                int rb = 64 * mw + 16 * mf;
                const float* p0 = &Xf[(rb + r) * 36 + kk * 16 + 2 * c];
                const float* p1 = &Xf[(rb + 8 + r) * 36 + kk * 16 + 2 * c];
                split2(*(const float2*)p0,       ah[mf][0], al[mf][0]);
                split2(*(const float2*)p1,       ah[mf][1], al[mf][1]);
                split2(*(const float2*)(p0 + 8), ah[mf][2], al[mf][2]);
                split2(*(const float2*)(p1 + 8), ah[mf][3], al[mf][3]);
            }
#pragma unroll
            for (int nf = 0; nf < 6; nf++) {
                int bi = (48 * nw + 8 * nf + r) * 20 + kk * 8 + c;
                uint32_t bh0 = Wh32[bi], bh1 = Wh32[bi + 4];
                uint32_t bl0 = Wl32[bi], bl1 = Wl32[bi + 4];
#pragma unroll
                for (int mf = 0; mf < 4; mf++) {
                    mma_f16(acc[mf][nf], ah[mf], bh0, bh1);
                    mma_f16(acc[mf][nf], ah[mf], bl0, bl1);
                    mma_f16(acc[mf][nf], al[mf], bh0, bh1);
                }
            }
        }
        __syncthreads();
    }

    // epilogue: n<64 -> k, 64..127 -> q (scaled into log2 domain), 128..191 -> v^T
    const float qs = SCALE * LOG2E;
#pragma unroll
    for (int mf = 0; mf < 4; mf++) {
#pragma unroll
        for (int nf = 0; nf < 6; nf++) {
            int n = 48 * nw + 8 * nf + 2 * c;
            int r0 = row0 + 64 * mw + 16 * mf + r;
            float v0 = acc[mf][nf][0], v1 = acc[mf][nf][1];
            float v2 = acc[mf][nf][2], v3 = acc[mf][nf][3];
            if (n < 64) {
                *(__half2*)&g_kh[(size_t)r0 * HH + n] = __floats2half2_rn(v0, v1);
                *(__half2*)&g_kh[(size_t)(r0 + 8) * HH + n] = __floats2half2_rn(v2, v3);
            } else if (n < 128) {
                *(__half2*)&g_qh[(size_t)r0 * HH + n - 64] =
                    __floats2half2_rn(v0 * qs, v1 * qs);
                *(__half2*)&g_qh[(size_t)(r0 + 8) * HH + n - 64] =
                    __floats2half2_rn(v2 * qs, v3 * qs);
            } else {
                int hh = n - 128;
                int b = r0 >> 12, t = r0 & 4095;
                size_t vb = (size_t)b * HH * TT;
                g_vt[vb + (size_t)hh * TT + t]       = __float2half_rn(v0);
                g_vt[vb + (size_t)(hh + 1) * TT + t] = __float2half_rn(v1);
                g_vt[vb + (size_t)hh * TT + t + 8]       = __float2half_rn(v2);
                g_vt[vb + (size_t)(hh + 1) * TT + t + 8] = __float2half_rn(v3);
            }
        }
    }
}

// ---------------------------------------------------------------------------
// Split-K flash attention partial, fp16 m16n8k16, ldmatrix + cp.async pipe.
// Softmax in exp2 domain. (R10 config, no register cap.)
// CTA = 256 thr (8 warps), Q tile 128 rows; warp w owns rows 16w..16w+15.
// ---------------------------------------------------------------------------
#define QB 0
#define KB 18432
#define KBUF 9216
#define VB 36864
#define ATTN_SMEM 55296

__global__ __launch_bounds__(256) void attn_partial()
{
    const int ch = blockIdx.x, qt = blockIdx.y, b = blockIdx.z;
    const int nkt = 2 * qt + 2;
    if (ch * CH >= nkt) return;

    extern __shared__ __half sma[];
    uint32_t sbase;
    asm("{ .reg .u64 t; cvta.to.shared.u64 t, %1; cvt.u32.u64 %0, t; }"
        : "=r"(sbase) : "l"(sma));

    const int tid = threadIdx.x;
    const int w = tid >> 5;
    const int lane = tid & 31;
    const int r = lane >> 2;
    const int c = lane & 3;
    const int rowA = 16 * w + r;
    const int q0 = qt * 128;
    const size_t base = (size_t)b * TT * HH;
    const size_t vbase = (size_t)b * HH * TT;
    const int unit = (b * 32 + qt) * 8 + ch;

    const uint32_t qa_lane = sbase + QB
        + (16 * w + (lane & 7) + ((lane >> 3) & 1) * 8) * 144
        + ((lane >> 4) & 1) * 16;
    const uint32_t b_lane =
        ((lane & 7) + ((lane >> 4) & 1) * 8) * 144 + ((lane >> 3) & 1) * 16;

    for (int i = tid; i < 128 * 8; i += 256) {
        int row = i >> 3, seg = i & 7;
        *(uint4*)((char*)sma + QB + row * 144 + seg * 16) =
            *(const uint4*)&g_qh[base + (size_t)(q0 + row) * HH + seg * 8];
    }

    const int kt_start = ch * CH;
    const int kt_end = min(kt_start + CH, nkt);

    auto issue = [&](int kt, int buf) {
        const int k0 = kt * 64;
        for (int i = tid; i < 512; i += 256) {
            int row = i >> 3, seg = i & 7;
            cp16(sbase + KB + buf * KBUF + row * 144 + seg * 16,
                 &g_kh[base + (size_t)(k0 + row) * HH + seg * 8]);
            cp16(sbase + VB + buf * KBUF + row * 144 + seg * 16,
                 &g_vt[vbase + (size_t)row * TT + k0 + seg * 8]);
        }
    };

    issue(kt_start, kt_start & 1);
    CP_COMMIT();

    float mA = -1e30f, mB = -1e30f, lA = 0.f, lB = 0.f;
    float o[8][4];
#pragma unroll
    for (int nf = 0; nf < 8; nf++)
#pragma unroll
        for (int j = 0; j < 4; j++) o[nf][j] = 0.f;

    for (int kt = kt_start; kt < kt_end; kt++) {
        const uint32_t kbuf = sbase + KB + (uint32_t)(kt & 1) * KBUF;
        const uint32_t vbuf = sbase + VB + (uint32_t)(kt & 1) * KBUF;
        CP_WAIT0();
        __syncthreads();
        if (kt + 1 < kt_end) {
            issue(kt + 1, (kt + 1) & 1);
            CP_COMMIT();
        }

        // S = Q K^T  (log2-domain logits)
        float s[8][4];
#pragma unroll
        for (int nf = 0; nf < 8; nf++)
#pragma unroll
            for (int j = 0; j < 4; j++) s[nf][j] = 0.f;
#pragma unroll
        for (int kk = 0; kk < 4; kk++) {
            uint32_t a[4];
            ldsm4(a[0], a[1], a[2], a[3], qa_lane + kk * 32);
#pragma unroll
            for (int nfp = 0; nfp < 4; nfp++) {
                uint32_t b0, b1, b2, b3;
                ldsm4(b0, b1, b2, b3,
                      kbuf + b_lane + (uint32_t)(nfp * 2304 + kk * 32));
                mma_f16(s[2 * nfp], a, b0, b1);
                mma_f16(s[2 * nfp + 1], a, b2, b3);
            }
        }

        if (kt >= nkt - 2) {
            int gA = q0 + rowA;
            int k0 = kt * 64;
#pragma unroll
            for (int nf = 0; nf < 8; nf++) {
                int col = k0 + nf * 8 + 2 * c;
                if (col > gA)     s[nf][0] = -1e30f;
                if (col + 1 > gA) s[nf][1] = -1e30f;
                if (col > gA + 8)     s[nf][2] = -1e30f;
                if (col + 1 > gA + 8) s[nf][3] = -1e30f;
            }
        }

        float xA = -1e30f, xB = -1e30f;
#pragma unroll
        for (int nf = 0; nf < 8; nf++) {
            xA = fmaxf(xA, fmaxf(s[nf][0], s[nf][1]));
            xB = fmaxf(xB, fmaxf(s[nf][2], s[nf][3]));
        }
#pragma unroll
        for (int d = 1; d < 4; d <<= 1) {
            xA = fmaxf(xA, __shfl_xor_sync(0xffffffffu, xA, d));
            xB = fmaxf(xB, __shfl_xor_sync(0xffffffffu, xB, d));
        }
        float mnA = fmaxf(mA, xA), mnB = fmaxf(mB, xB);
        float aA = exp2f(mA - mnA), aB = exp2f(mB - mnB);

        uint32_t pp[8][2];
        float sumA = 0.f, sumB = 0.f;
#pragma unroll
        for (int nf = 0; nf < 8; nf++) {
            float p0 = exp2f(s[nf][0] - mnA);
            float p1 = exp2f(s[nf][1] - mnA);
            float p2 = exp2f(s[nf][2] - mnB);
            float p3 = exp2f(s[nf][3] - mnB);
            sumA += p0 + p1;
            sumB += p2 + p3;
            pp[nf][0] = h2u(__floats2half2_rn(p0, p1));
            pp[nf][1] = h2u(__floats2half2_rn(p2, p3));
        }
#pragma unroll
        for (int d = 1; d < 4; d <<= 1) {
            sumA += __shfl_xor_sync(0xffffffffu, sumA, d);
            sumB += __shfl_xor_sync(0xffffffffu, sumB, d);
        }
        lA = lA * aA + sumA;
        lB = lB * aB + sumB;
        mA = mnA;
        mB = mnB;
#pragma unroll
        for (int nf = 0; nf < 8; nf++) {
            o[nf][0] *= aA; o[nf][1] *= aA;
            o[nf][2] *= aB; o[nf][3] *= aB;
        }

        // O += P V
#pragma unroll
        for (int kk = 0; kk < 4; kk++) {
            uint32_t a[4] = { pp[2 * kk][0], pp[2 * kk][1],
                              pp[2 * kk + 1][0], pp[2 * kk + 1][1] };
#pragma unroll
            for (int nfp = 0; nfp < 4; nfp++) {
                uint32_t b0, b1, b2, b3;
                ldsm4(b0, b1, b2, b3,
                      vbuf + b_lane + (uint32_t)(nfp * 2304 + kk * 32));
                mma_f16(o[2 * nfp], a, b0, b1);
                mma_f16(o[2 * nfp + 1], a, b2, b3);
            }
        }
    }

    // write partial O (unnormalized, fp16) + per-row m, l (fp32)
    __half2* op = (__half2*)g_opart;
#pragma unroll
    for (int nf = 0; nf < 8; nf++) {
        int colo = nf * 8 + 2 * c;
        op[((size_t)unit * 8192 + rowA * 64 + colo) >> 1] =
            __floats2half2_rn(o[nf][0], o[nf][1]);
        op[((size_t)unit * 8192 + (rowA + 8) * 64 + colo) >> 1] =
            __floats2half2_rn(o[nf][2], o[nf][3]);
    }
    if (c == 0) {
        g_mpart[unit * 128 + rowA] = mA;
        g_mpart[unit * 128 + rowA + 8] = mB;
        g_lpart[unit * 128 + rowA] = lA;
        g_lpart[unit * 128 + rowA + 8] = lB;
    }
}

// ---------------------------------------------------------------------------
// Combine: LSE-merge (log2 domain) up to 8 fp16 chunk partials.
// grid (32, BB, 4): z = row quarter. 256 thr: row = rz*32 + tid>>3, 8 cols each.
// ---------------------------------------------------------------------------
__global__ __launch_bounds__(256) void attn_combine(float* __restrict__ out)
{
    const int qt = blockIdx.x, b = blockIdx.y, rq = blockIdx.z;
    const int tid = threadIdx.x;
    const int row = rq * 32 + (tid >> 3);
    const int co = (tid & 7) * 8;
    const int nch = (2 * qt + 2 + CH - 1) / CH;
    const int ubase = (b * 32 + qt) * 8;

    float M = -1e30f;
    for (int i = 0; i < nch; i++)
        M = fmaxf(M, g_mpart[(ubase + i) * 128 + row]);

    float L = 0.f;
    float acc[8];
#pragma unroll
    for (int j = 0; j < 8; j++) acc[j] = 0.f;

    for (int i = 0; i < nch; i++) {
        float coef = exp2f(g_mpart[(ubase + i) * 128 + row] - M);
        L += coef * g_lpart[(ubase + i) * 128 + row];
        // 8 fp16 values = 16 bytes
        const __half2* src = (const __half2*)
            &g_opart[(size_t)(ubase + i) * 8192 + row * 64 + co];
        uint4 raw = *(const uint4*)src;
        __half2 h0 = *(__half2*)&raw.x;
        __half2 h1 = *(__half2*)&raw.y;
        __half2 h2 = *(__half2*)&raw.z;
        __half2 h3 = *(__half2*)&raw.w;
        float2 f0 = __half22float2(h0), f1 = __half22float2(h1);
        float2 f2 = __half22float2(h2), f3 = __half22float2(h3);
        acc[0] += coef * f0.x; acc[1] += coef * f0.y;
        acc[2] += coef * f1.x; acc[3] += coef * f1.y;
        acc[4] += coef * f2.x; acc[5] += coef * f2.y;
        acc[6] += coef * f3.x; acc[7] += coef * f3.y;
    }

    float inv = 1.f / L;
    float* dst = &out[(size_t)b * TT * HH + (size_t)(qt * 128 + row) * HH + co];
#pragma unroll
    for (int j = 0; j < 2; j++) {
        float4 v = make_float4(acc[4 * j] * inv, acc[4 * j + 1] * inv,
                               acc[4 * j + 2] * inv, acc[4 * j + 3] * inv);
        *(float4*)&dst[4 * j] = v;
    }
}

// ---------------------------------------------------------------------------
extern "C" void kernel_launch(void* const* d_in, const int* in_sizes, int n_in,
                              void* d_out, int out_size)
{
    const float* x  = (const float*)d_in[0];
    const float* Wk = (const float*)d_in[1];
    const float* Wq = (const float*)d_in[2];
    const float* Wv = (const float*)d_in[3];
    float* out = (float*)d_out;

    cudaFuncSetAttribute(proj_mma, cudaFuncAttributeMaxDynamicSharedMemorySize, PSMEM);
    cudaFuncSetAttribute(attn_partial, cudaFuncAttributeMaxDynamicSharedMemorySize, ATTN_SMEM);

    wsplit_kernel<<<384, 256>>>(Wk, Wq, Wv);
    proj_mma<<<128, 256, PSMEM>>>(x);
    attn_partial<<<dim3(8, 32, BB), 256, ATTN_SMEM>>>();
    attn_combine<<<dim3(32, BB, 4), 256>>>(out);
}

// round 15
// speedup vs baseline: 1.5212x; 1.0497x over previous
#include <cuda_runtime.h>
#include <cuda_fp16.h>
#include <cstdint>

#define BB 4
#define TT 4096
#define CC 512
#define HH 64
#define LOG2E 1.4426950408889634f
#define SCALE 0.044194173824159216f   // 512^-0.5
#define CH 8                           // k-tiles (64 keys) per split-K chunk

// fp16 operands
__device__ __half g_qh[BB * TT * HH];      // q * SCALE * log2e, [tok][h]
__device__ __half g_kh[BB * TT * HH];      // k, [tok][h]
__device__ __half g_vt[BB * HH * TT];      // v transposed, [b][h][t]
__device__ __half g_wh[192 * CC];          // W^T hi, [n][k]
__device__ __half g_wl[192 * CC];          // W^T lo
// split-K partials; O fp16, m/l fp32 (log2 domain)
__device__ __half g_opart[1024 * 128 * 64];
__device__ float g_mpart[1024 * 128];
__device__ float g_lpart[1024 * 128];

__device__ __forceinline__ uint32_t h2u(__half2 h) {
    union { __half2 h; uint32_t u; } cvt;
    cvt.h = h;
    return cvt.u;
}

__device__ __forceinline__ void mma_f16(float* d, const uint32_t* a,
                                        uint32_t b0, uint32_t b1) {
    asm volatile(
        "mma.sync.aligned.m16n8k16.row.col.f32.f16.f16.f32 "
        "{%0,%1,%2,%3}, {%4,%5,%6,%7}, {%8,%9}, {%0,%1,%2,%3};"
        : "+f"(d[0]), "+f"(d[1]), "+f"(d[2]), "+f"(d[3])
        : "r"(a[0]), "r"(a[1]), "r"(a[2]), "r"(a[3]), "r"(b0), "r"(b1));
}

__device__ __forceinline__ void ldsm4(uint32_t& r0, uint32_t& r1,
                                      uint32_t& r2, uint32_t& r3, uint32_t addr) {
    asm volatile(
        "ldmatrix.sync.aligned.m8n8.x4.shared.b16 {%0,%1,%2,%3}, [%4];"
        : "=r"(r0), "=r"(r1), "=r"(r2), "=r"(r3) : "r"(addr));
}

__device__ __forceinline__ void cp16(uint32_t dst, const void* src) {
    asm volatile("cp.async.cg.shared.global [%0], [%1], 16;"
                 :: "r"(dst), "l"(src) : "memory");
}
#define CP_COMMIT() asm volatile("cp.async.commit_group;" ::: "memory")
#define CP_WAIT1() asm volatile("cp.async.wait_group 1;" ::: "memory")
#define CP_WAIT0() asm volatile("cp.async.wait_group 0;" ::: "memory")

// ---------------------------------------------------------------------------
// W transpose + fp16 hi/lo split
// ---------------------------------------------------------------------------
__global__ __launch_bounds__(256) void wsplit_kernel(
    const float* __restrict__ Wk,
    const float* __restrict__ Wq,
    const float* __restrict__ Wv)
{
    int idx = blockIdx.x * 256 + threadIdx.x;   // 384 x 256 = 98304 = 192*512
    int k = idx / 192, n = idx - k * 192;
    const float* W = (n < 64) ? Wk : (n < 128) ? Wq : Wv;
    float w = W[k * HH + (n & 63)];
    __half hi = __float2half_rn(w);
    g_wh[n * CC + k] = hi;
    g_wl[n * CC + k] = __float2half_rn(w - __half2float(hi));
}

// ---------------------------------------------------------------------------
// Projection: fp16 2-term (xh*wh + xh*wl), m16n8k16, fp32 accum.
// x staged fp32 via cp.async, rounded to fp16 in registers.
// CTA 256 thr (8 warps): tile M=64 x N=192, K-chunk 32, double-buffer, grid 256.
// Warp (mw = w>>2 in 0..1, nw = w&3): 32x48 warp tile (2 mf x 6 nf).
// ---------------------------------------------------------------------------
#define PXB(buf) ((buf) * 9216)
#define PWB(buf) (18432 + (buf) * 30720)
#define PWLO 15360
#define PSMEM 79872

__global__ __launch_bounds__(256) void proj_mma(const float* __restrict__ x)
{
    extern __shared__ char smp[];
    uint32_t sbase;
    asm("{ .reg .u64 t; cvta.to.shared.u64 t, %1; cvt.u32.u64 %0, t; }"
        : "=r"(sbase) : "l"(smp));

    const int tid = threadIdx.x;
    const int w = tid >> 5;
    const int lane = tid & 31;
    const int r = lane >> 2;
    const int c = lane & 3;
    const int mw = w >> 2, nw = w & 3;
    const int row0 = blockIdx.x * 64;

    float acc[2][6][4];
#pragma unroll
    for (int mf = 0; mf < 2; mf++)
#pragma unroll
        for (int nf = 0; nf < 6; nf++)
#pragma unroll
            for (int j = 0; j < 4; j++) acc[mf][nf][j] = 0.f;

    auto issue = [&](int ck, int buf) {
        const int k0 = ck * 32;
        for (int t = tid; t < 512; t += 256) {        // X fp32: 64 rows x 8 segs
            int rr = t >> 3, seg = t & 7;
            cp16(sbase + PXB(buf) + rr * 144 + seg * 16,
                 &x[(size_t)(row0 + rr) * CC + k0 + seg * 4]);
        }
        for (int t = tid; t < 768; t += 256) {        // W hi+lo: 192 rows x 4 segs
            int n = t >> 2, seg = t & 3;
            cp16(sbase + PWB(buf) + n * 80 + seg * 16,
                 &g_wh[n * CC + k0 + seg * 8]);
            cp16(sbase + PWB(buf) + PWLO + n * 80 + seg * 16,
                 &g_wl[n * CC + k0 + seg * 8]);
        }
    };

    issue(0, 0);
    CP_COMMIT();

    for (int ck = 0; ck < 16; ck++) {
        const int buf = ck & 1;
        if (ck + 1 < 16) {
            issue(ck + 1, buf ^ 1);
            CP_COMMIT();
            CP_WAIT1();
        } else {
            CP_WAIT0();
        }
        __syncthreads();

        const float* Xf = (const float*)(smp + PXB(buf));
        const uint32_t* Wh32 = (const uint32_t*)(smp + PWB(buf));
        const uint32_t* Wl32 = (const uint32_t*)(smp + PWB(buf) + PWLO);

#pragma unroll
        for (int kk = 0; kk < 2; kk++) {
            uint32_t ah[2][4];
#pragma unroll
            for (int mf = 0; mf < 2; mf++) {
                int rb = 32 * mw + 16 * mf;
                const float* p0 = &Xf[(rb + r) * 36 + kk * 16 + 2 * c];
                const float* p1 = &Xf[(rb + 8 + r) * 36 + kk * 16 + 2 * c];
                float2 v0 = *(const float2*)p0;
                float2 v1 = *(const float2*)p1;
                float2 v2 = *(const float2*)(p0 + 8);
                float2 v3 = *(const float2*)(p1 + 8);
                ah[mf][0] = h2u(__floats2half2_rn(v0.x, v0.y));
                ah[mf][1] = h2u(__floats2half2_rn(v1.x, v1.y));
                ah[mf][2] = h2u(__floats2half2_rn(v2.x, v2.y));
                ah[mf][3] = h2u(__floats2half2_rn(v3.x, v3.y));
            }
#pragma unroll
            for (int nf = 0; nf < 6; nf++) {
                int bi = (48 * nw + 8 * nf + r) * 20 + kk * 8 + c;
                uint32_t bh0 = Wh32[bi], bh1 = Wh32[bi + 4];
                uint32_t bl0 = Wl32[bi], bl1 = Wl32[bi + 4];
#pragma unroll
                for (int mf = 0; mf < 2; mf++) {
                    mma_f16(acc[mf][nf], ah[mf], bh0, bh1);
                    mma_f16(acc[mf][nf], ah[mf], bl0, bl1);
                }
            }
        }
        __syncthreads();
    }

    // epilogue: n<64 -> k, 64..127 -> q (scaled into log2 domain), 128..191 -> v^T
    const float qs = SCALE * LOG2E;
#pragma unroll
    for (int mf = 0; mf < 2; mf++) {
#pragma unroll
        for (int nf = 0; nf < 6; nf++) {
            int n = 48 * nw + 8 * nf + 2 * c;
            int r0 = row0 + 32 * mw + 16 * mf + r;
            float v0 = acc[mf][nf][0], v1 = acc[mf][nf][1];
            float v2 = acc[mf][nf][2], v3 = acc[mf][nf][3];
            if (n < 64) {
                *(__half2*)&g_kh[(size_t)r0 * HH + n] = __floats2half2_rn(v0, v1);
                *(__half2*)&g_kh[(size_t)(r0 + 8) * HH + n] = __floats2half2_rn(v2, v3);
            } else if (n < 128) {
                *(__half2*)&g_qh[(size_t)r0 * HH + n - 64] =
                    __floats2half2_rn(v0 * qs, v1 * qs);
                *(__half2*)&g_qh[(size_t)(r0 + 8) * HH + n - 64] =
                    __floats2half2_rn(v2 * qs, v3 * qs);
            } else {
                int hh = n - 128;
                int b = r0 >> 12, t = r0 & 4095;
                size_t vb = (size_t)b * HH * TT;
                g_vt[vb + (size_t)hh * TT + t]       = __float2half_rn(v0);
                g_vt[vb + (size_t)(hh + 1) * TT + t] = __float2half_rn(v1);
                g_vt[vb + (size_t)hh * TT + t + 8]       = __float2half_rn(v2);
                g_vt[vb + (size_t)(hh + 1) * TT + t + 8] = __float2half_rn(v3);
            }
        }
    }
}

// ---------------------------------------------------------------------------
// Split-K flash attention partial (unchanged from R14 / best config).
// fp16 m16n8k16, ldmatrix + cp.async pipe, exp2-domain softmax.
// CTA = 256 thr (8 warps), Q tile 128 rows; warp w owns rows 16w..16w+15.
// ---------------------------------------------------------------------------
#define QB 0
#define KB 18432
#define KBUF 9216
#define VB 36864
#define ATTN_SMEM 55296

__global__ __launch_bounds__(256) void attn_partial()
{
    const int ch = blockIdx.x, qt = blockIdx.y, b = blockIdx.z;
    const int nkt = 2 * qt + 2;
    if (ch * CH >= nkt) return;

    extern __shared__ __half sma[];
    uint32_t sbase;
    asm("{ .reg .u64 t; cvta.to.shared.u64 t, %1; cvt.u32.u64 %0, t; }"
        : "=r"(sbase) : "l"(sma));

    const int tid = threadIdx.x;
    const int w = tid >> 5;
    const int lane = tid & 31;
    const int r = lane >> 2;
    const int c = lane & 3;
    const int rowA = 16 * w + r;
    const int q0 = qt * 128;
    const size_t base = (size_t)b * TT * HH;
    const size_t vbase = (size_t)b * HH * TT;
    const int unit = (b * 32 + qt) * 8 + ch;

    const uint32_t qa_lane = sbase + QB
        + (16 * w + (lane & 7) + ((lane >> 3) & 1) * 8) * 144
        + ((lane >> 4) & 1) * 16;
    const uint32_t b_lane =
        ((lane & 7) + ((lane >> 4) & 1) * 8) * 144 + ((lane >> 3) & 1) * 16;

    for (int i = tid; i < 128 * 8; i += 256) {
        int row = i >> 3, seg = i & 7;
        *(uint4*)((char*)sma + QB + row * 144 + seg * 16) =
            *(const uint4*)&g_qh[base + (size_t)(q0 + row) * HH + seg * 8];
    }

    const int kt_start = ch * CH;
    const int kt_end = min(kt_start + CH, nkt);

    auto issue = [&](int kt, int buf) {
        const int k0 = kt * 64;
        for (int i = tid; i < 512; i += 256) {
            int row = i >> 3, seg = i & 7;
            cp16(sbase + KB + buf * KBUF + row * 144 + seg * 16,
                 &g_kh[base + (size_t)(k0 + row) * HH + seg * 8]);
            cp16(sbase + VB + buf * KBUF + row * 144 + seg * 16,
                 &g_vt[vbase + (size_t)row * TT + k0 + seg * 8]);
        }
    };

    issue(kt_start, kt_start & 1);
    CP_COMMIT();

    float mA = -1e30f, mB = -1e30f, lA = 0.f, lB = 0.f;
    float o[8][4];
#pragma unroll
    for (int nf = 0; nf < 8; nf++)
#pragma unroll
        for (int j = 0; j < 4; j++) o[nf][j] = 0.f;

    for (int kt = kt_start; kt < kt_end; kt++) {
        const uint32_t kbuf = sbase + KB + (uint32_t)(kt & 1) * KBUF;
        const uint32_t vbuf = sbase + VB + (uint32_t)(kt & 1) * KBUF;
        CP_WAIT0();
        __syncthreads();
        if (kt + 1 < kt_end) {
            issue(kt + 1, (kt + 1) & 1);
            CP_COMMIT();
        }

        // S = Q K^T  (log2-domain logits)
        float s[8][4];
#pragma unroll
        for (int nf = 0; nf < 8; nf++)
#pragma unroll
            for (int j = 0; j < 4; j++) s[nf][j] = 0.f;
#pragma unroll
        for (int kk = 0; kk < 4; kk++) {
            uint32_t a[4];
            ldsm4(a[0], a[1], a[2], a[3], qa_lane + kk * 32);
#pragma unroll
            for (int nfp = 0; nfp < 4; nfp++) {
                uint32_t b0, b1, b2, b3;
                ldsm4(b0, b1, b2, b3,
                      kbuf + b_lane + (uint32_t)(nfp * 2304 + kk * 32));
                mma_f16(s[2 * nfp], a, b0, b1);
                mma_f16(s[2 * nfp + 1], a, b2, b3);
            }
        }

        if (kt >= nkt - 2) {
            int gA = q0 + rowA;
            int k0 = kt * 64;
#pragma unroll
            for (int nf = 0; nf < 8; nf++) {
                int col = k0 + nf * 8 + 2 * c;
                if (col > gA)     s[nf][0] = -1e30f;
                if (col + 1 > gA) s[nf][1] = -1e30f;
                if (col > gA + 8)     s[nf][2] = -1e30f;
                if (col + 1 > gA + 8) s[nf][3] = -1e30f;
            }
        }

        float xA = -1e30f, xB = -1e30f;
#pragma unroll
        for (int nf = 0; nf < 8; nf++) {
            xA = fmaxf(xA, fmaxf(s[nf][0], s[nf][1]));
            xB = fmaxf(xB, fmaxf(s[nf][2], s[nf][3]));
        }
#pragma unroll
        for (int d = 1; d < 4; d <<= 1) {
            xA = fmaxf(xA, __shfl_xor_sync(0xffffffffu, xA, d));
            xB = fmaxf(xB, __shfl_xor_sync(0xffffffffu, xB, d));
        }
        float mnA = fmaxf(mA, xA), mnB = fmaxf(mB, xB);
        float aA = exp2f(mA - mnA), aB = exp2f(mB - mnB);

        uint32_t pp[8][2];
        float sumA = 0.f, sumB = 0.f;
#pragma unroll
        for (int nf = 0; nf < 8; nf++) {
            float p0 = exp2f(s[nf][0] - mnA);
            float p1 = exp2f(s[nf][1] - mnA);
            float p2 = exp2f(s[nf][2] - mnB);
            float p3 = exp2f(s[nf][3] - mnB);
            sumA += p0 + p1;
            sumB += p2 + p3;
            pp[nf][0] = h2u(__floats2half2_rn(p0, p1));
            pp[nf][1] = h2u(__floats2half2_rn(p2, p3));
        }
#pragma unroll
        for (int d = 1; d < 4; d <<= 1) {
            sumA += __shfl_xor_sync(0xffffffffu, sumA, d);
            sumB += __shfl_xor_sync(0xffffffffu, sumB, d);
        }
        lA = lA * aA + sumA;
        lB = lB * aB + sumB;
        mA = mnA;
        mB = mnB;
#pragma unroll
        for (int nf = 0; nf < 8; nf++) {
            o[nf][0] *= aA; o[nf][1] *= aA;
            o[nf][2] *= aB; o[nf][3] *= aB;
        }

        // O += P V
#pragma unroll
        for (int kk = 0; kk < 4; kk++) {
            uint32_t a[4] = { pp[2 * kk][0], pp[2 * kk][1],
                              pp[2 * kk + 1][0], pp[2 * kk + 1][1] };
#pragma unroll
            for (int nfp = 0; nfp < 4; nfp++) {
                uint32_t b0, b1, b2, b3;
                ldsm4(b0, b1, b2, b3,
                      vbuf + b_lane + (uint32_t)(nfp * 2304 + kk * 32));
                mma_f16(o[2 * nfp], a, b0, b1);
                mma_f16(o[2 * nfp + 1], a, b2, b3);
            }
        }
    }

    // write partial O (unnormalized, fp16) + per-row m, l (fp32)
    __half2* op = (__half2*)g_opart;
#pragma unroll
    for (int nf = 0; nf < 8; nf++) {
        int colo = nf * 8 + 2 * c;
        op[((size_t)unit * 8192 + rowA * 64 + colo) >> 1] =
            __floats2half2_rn(o[nf][0], o[nf][1]);
        op[((size_t)unit * 8192 + (rowA + 8) * 64 + colo) >> 1] =
            __floats2half2_rn(o[nf][2], o[nf][3]);
    }
    if (c == 0) {
        g_mpart[unit * 128 + rowA] = mA;
        g_mpart[unit * 128 + rowA + 8] = mB;
        g_lpart[unit * 128 + rowA] = lA;
        g_lpart[unit * 128 + rowA + 8] = lB;
    }
}

// ---------------------------------------------------------------------------
// Combine: LSE-merge (log2 domain), MLP-batched loads of <=8 fp16 partials.
// grid (32, BB, 4): z = row quarter. 256 thr: row = rq*32 + tid>>3, 8 cols each.
// ---------------------------------------------------------------------------
__global__ __launch_bounds__(256) void attn_combine(float* __restrict__ out)
{
    const int qt = blockIdx.x, b = blockIdx.y, rq = blockIdx.z;
    const int tid = threadIdx.x;
    const int row = rq * 32 + (tid >> 3);
    const int co = (tid & 7) * 8;
    const int nch = (2 * qt + 2 + CH - 1) / CH;
    const int ubase = (b * 32 + qt) * 8;

    // batch all scalar loads (independent -> MLP)
    float mv[8], lv[8];
#pragma unroll
    for (int i = 0; i < 8; i++) {
        mv[i] = (i < nch) ? g_mpart[(ubase + i) * 128 + row] : -1e30f;
        lv[i] = (i < nch) ? g_lpart[(ubase + i) * 128 + row] : 0.f;
    }
    // batch all O-tile loads (independent -> MLP 8)
    uint4 raws[8];
#pragma unroll
    for (int i = 0; i < 8; i++) {
        if (i < nch)
            raws[i] = *(const uint4*)
                &g_opart[(size_t)(ubase + i) * 8192 + row * 64 + co];
    }

    float M = -1e30f;
#pragma unroll
    for (int i = 0; i < 8; i++) M = fmaxf(M, mv[i]);

    float L = 0.f;
    float acc[8];
#pragma unroll
    for (int j = 0; j < 8; j++) acc[j] = 0.f;

#pragma unroll
    for (int i = 0; i < 8; i++) {
        if (i >= nch) break;
        float coef = exp2f(mv[i] - M);
        L += coef * lv[i];
        __half2 h0 = *(__half2*)&raws[i].x;
        __half2 h1 = *(__half2*)&raws[i].y;
        __half2 h2 = *(__half2*)&raws[i].z;
        __half2 h3 = *(__half2*)&raws[i].w;
        float2 f0 = __half22float2(h0), f1 = __half22float2(h1);
        float2 f2 = __half22float2(h2), f3 = __half22float2(h3);
        acc[0] += coef * f0.x; acc[1] += coef * f0.y;
        acc[2] += coef * f1.x; acc[3] += coef * f1.y;
        acc[4] += coef * f2.x; acc[5] += coef * f2.y;
        acc[6] += coef * f3.x; acc[7] += coef * f3.y;
    }

    float inv = 1.f / L;
    float* dst = &out[(size_t)b * TT * HH + (size_t)(qt * 128 + row) * HH + co];
#pragma unroll
    for (int j = 0; j < 2; j++) {
        float4 v = make_float4(acc[4 * j] * inv, acc[4 * j + 1] * inv,
                               acc[4 * j + 2] * inv, acc[4 * j + 3] * inv);
        *(float4*)&dst[4 * j] = v;
    }
}

// ---------------------------------------------------------------------------
extern "C" void kernel_launch(void* const* d_in, const int* in_sizes, int n_in,
                              void* d_out, int out_size)
{
    const float* x  = (const float*)d_in[0];
    const float* Wk = (const float*)d_in[1];
    const float* Wq = (const float*)d_in[2];
    const float* Wv = (const float*)d_in[3];
    float* out = (float*)d_out;

    cudaFuncSetAttribute(proj_mma, cudaFuncAttributeMaxDynamicSharedMemorySize, PSMEM);
    cudaFuncSetAttribute(attn_partial, cudaFuncAttributeMaxDynamicSharedMemorySize, ATTN_SMEM);

    wsplit_kernel<<<384, 256>>>(Wk, Wq, Wv);
    proj_mma<<<256, 256, PSMEM>>>(x);
    attn_partial<<<dim3(8, 32, BB), 256, ATTN_SMEM>>>();
    attn_combine<<<dim3(32, BB, 4), 256>>>(out);
}

// round 16
// speedup vs baseline: 1.5599x; 1.0255x over previous
#include <cuda_runtime.h>
#include <cuda_fp16.h>
#include <cstdint>

#define BB 4
#define TT 4096
#define CC 512
#define HH 64
#define LOG2E 1.4426950408889634f
#define SCALE 0.044194173824159216f   // 512^-0.5
#define CH 8                           // k-tiles (64 keys) per split-K chunk

// fp16 operands
__device__ __half g_qh[BB * TT * HH];      // q * SCALE * log2e, [tok][h]
__device__ __half g_kh[BB * TT * HH];      // k, [tok][h]
__device__ __half g_vt[BB * HH * TT];      // v transposed, [b][h][t]
__device__ __half g_wh[192 * CC];          // W^T hi, [n][k]
__device__ __half g_wl[192 * CC];          // W^T lo
// split-K partials; O fp16, m/l fp32 (log2 domain)
__device__ __half g_opart[1024 * 128 * 64];
__device__ float g_mpart[1024 * 128];
__device__ float g_lpart[1024 * 128];

#define ONES_H2 0x3C003C00u   // half2(1.0, 1.0)

__device__ __forceinline__ uint32_t h2u(__half2 h) {
    union { __half2 h; uint32_t u; } cvt;
    cvt.h = h;
    return cvt.u;
}

// packed exp2: (lo, hi) fp32 -> fp16x2 -> ex2.approx.f16x2
__device__ __forceinline__ uint32_t exp2h2(float lo, float hi) {
    uint32_t d;
    asm("{\n\t.reg .b32 t;\n\t"
        "cvt.rn.f16x2.f32 t, %1, %2;\n\t"
        "ex2.approx.f16x2 %0, t;\n\t}"
        : "=r"(d) : "f"(hi), "f"(lo));
    return d;
}

__device__ __forceinline__ void mma_f16(float* d, const uint32_t* a,
                                        uint32_t b0, uint32_t b1) {
    asm volatile(
        "mma.sync.aligned.m16n8k16.row.col.f32.f16.f16.f32 "
        "{%0,%1,%2,%3}, {%4,%5,%6,%7}, {%8,%9}, {%0,%1,%2,%3};"
        : "+f"(d[0]), "+f"(d[1]), "+f"(d[2]), "+f"(d[3])
        : "r"(a[0]), "r"(a[1]), "r"(a[2]), "r"(a[3]), "r"(b0), "r"(b1));
}

__device__ __forceinline__ void ldsm4(uint32_t& r0, uint32_t& r1,
                                      uint32_t& r2, uint32_t& r3, uint32_t addr) {
    asm volatile(
        "ldmatrix.sync.aligned.m8n8.x4.shared.b16 {%0,%1,%2,%3}, [%4];"
        : "=r"(r0), "=r"(r1), "=r"(r2), "=r"(r3) : "r"(addr));
}

__device__ __forceinline__ void cp16(uint32_t dst, const void* src) {
    asm volatile("cp.async.cg.shared.global [%0], [%1], 16;"
                 :: "r"(dst), "l"(src) : "memory");
}
#define CP_COMMIT() asm volatile("cp.async.commit_group;" ::: "memory")
#define CP_WAIT1() asm volatile("cp.async.wait_group 1;" ::: "memory")
#define CP_WAIT0() asm volatile("cp.async.wait_group 0;" ::: "memory")

// ---------------------------------------------------------------------------
// W transpose + fp16 hi/lo split
// ---------------------------------------------------------------------------
__global__ __launch_bounds__(256) void wsplit_kernel(
    const float* __restrict__ Wk,
    const float* __restrict__ Wq,
    const float* __restrict__ Wv)
{
    int idx = blockIdx.x * 256 + threadIdx.x;   // 384 x 256 = 98304 = 192*512
    int k = idx / 192, n = idx - k * 192;
    const float* W = (n < 64) ? Wk : (n < 128) ? Wq : Wv;
    float w = W[k * HH + (n & 63)];
    __half hi = __float2half_rn(w);
    g_wh[n * CC + k] = hi;
    g_wl[n * CC + k] = __float2half_rn(w - __half2float(hi));
}

// ---------------------------------------------------------------------------
// Projection: fp16 2-term (xh*wh + xh*wl), m16n8k16, fp32 accum. (R15 config)
// CTA 256 thr: tile M=64 x N=192, K-chunk 32, double-buffer, grid 256.
// ---------------------------------------------------------------------------
#define PXB(buf) ((buf) * 9216)
#define PWB(buf) (18432 + (buf) * 30720)
#define PWLO 15360
#define PSMEM 79872

__global__ __launch_bounds__(256) void proj_mma(const float* __restrict__ x)
{
    extern __shared__ char smp[];
    uint32_t sbase;
    asm("{ .reg .u64 t; cvta.to.shared.u64 t, %1; cvt.u32.u64 %0, t; }"
        : "=r"(sbase) : "l"(smp));

    const int tid = threadIdx.x;
    const int w = tid >> 5;
    const int lane = tid & 31;
    const int r = lane >> 2;
    const int c = lane & 3;
    const int mw = w >> 2, nw = w & 3;
    const int row0 = blockIdx.x * 64;

    float acc[2][6][4];
#pragma unroll
    for (int mf = 0; mf < 2; mf++)
#pragma unroll
        for (int nf = 0; nf < 6; nf++)
#pragma unroll
            for (int j = 0; j < 4; j++) acc[mf][nf][j] = 0.f;

    auto issue = [&](int ck, int buf) {
        const int k0 = ck * 32;
        for (int t = tid; t < 512; t += 256) {        // X fp32: 64 rows x 8 segs
            int rr = t >> 3, seg = t & 7;
            cp16(sbase + PXB(buf) + rr * 144 + seg * 16,
                 &x[(size_t)(row0 + rr) * CC + k0 + seg * 4]);
        }
        for (int t = tid; t < 768; t += 256) {        // W hi+lo: 192 rows x 4 segs
            int n = t >> 2, seg = t & 3;
            cp16(sbase + PWB(buf) + n * 80 + seg * 16,
                 &g_wh[n * CC + k0 + seg * 8]);
            cp16(sbase + PWB(buf) + PWLO + n * 80 + seg * 16,
                 &g_wl[n * CC + k0 + seg * 8]);
        }
    };

    issue(0, 0);
    CP_COMMIT();

    for (int ck = 0; ck < 16; ck++) {
        const int buf = ck & 1;
        if (ck + 1 < 16) {
            issue(ck + 1, buf ^ 1);
            CP_COMMIT();
            CP_WAIT1();
        } else {
            CP_WAIT0();
        }
        __syncthreads();

        const float* Xf = (const float*)(smp + PXB(buf));
        const uint32_t* Wh32 = (const uint32_t*)(smp + PWB(buf));
        const uint32_t* Wl32 = (const uint32_t*)(smp + PWB(buf) + PWLO);

#pragma unroll
        for (int kk = 0; kk < 2; kk++) {
            uint32_t ah[2][4];
#pragma unroll
            for (int mf = 0; mf < 2; mf++) {
                int rb = 32 * mw + 16 * mf;
                const float* p0 = &Xf[(rb + r) * 36 + kk * 16 + 2 * c];
                const float* p1 = &Xf[(rb + 8 + r) * 36 + kk * 16 + 2 * c];
                float2 v0 = *(const float2*)p0;
                float2 v1 = *(const float2*)p1;
                float2 v2 = *(const float2*)(p0 + 8);
                float2 v3 = *(const float2*)(p1 + 8);
                ah[mf][0] = h2u(__floats2half2_rn(v0.x, v0.y));
                ah[mf][1] = h2u(__floats2half2_rn(v1.x, v1.y));
                ah[mf][2] = h2u(__floats2half2_rn(v2.x, v2.y));
                ah[mf][3] = h2u(__floats2half2_rn(v3.x, v3.y));
            }
#pragma unroll
            for (int nf = 0; nf < 6; nf++) {
                int bi = (48 * nw + 8 * nf + r) * 20 + kk * 8 + c;
                uint32_t bh0 = Wh32[bi], bh1 = Wh32[bi + 4];
                uint32_t bl0 = Wl32[bi], bl1 = Wl32[bi + 4];
#pragma unroll
                for (int mf = 0; mf < 2; mf++) {
                    mma_f16(acc[mf][nf], ah[mf], bh0, bh1);
                    mma_f16(acc[mf][nf], ah[mf], bl0, bl1);
                }
            }
        }
        __syncthreads();
    }

    // epilogue: n<64 -> k, 64..127 -> q (scaled into log2 domain), 128..191 -> v^T
    const float qs = SCALE * LOG2E;
#pragma unroll
    for (int mf = 0; mf < 2; mf++) {
#pragma unroll
        for (int nf = 0; nf < 6; nf++) {
            int n = 48 * nw + 8 * nf + 2 * c;
            int r0 = row0 + 32 * mw + 16 * mf + r;
            float v0 = acc[mf][nf][0], v1 = acc[mf][nf][1];
            float v2 = acc[mf][nf][2], v3 = acc[mf][nf][3];
            if (n < 64) {
                *(__half2*)&g_kh[(size_t)r0 * HH + n] = __floats2half2_rn(v0, v1);
                *(__half2*)&g_kh[(size_t)(r0 + 8) * HH + n] = __floats2half2_rn(v2, v3);
            } else if (n < 128) {
                *(__half2*)&g_qh[(size_t)r0 * HH + n - 64] =
                    __floats2half2_rn(v0 * qs, v1 * qs);
                *(__half2*)&g_qh[(size_t)(r0 + 8) * HH + n - 64] =
                    __floats2half2_rn(v2 * qs, v3 * qs);
            } else {
                int hh = n - 128;
                int b = r0 >> 12, t = r0 & 4095;
                size_t vb = (size_t)b * HH * TT;
                g_vt[vb + (size_t)hh * TT + t]       = __float2half_rn(v0);
                g_vt[vb + (size_t)(hh + 1) * TT + t] = __float2half_rn(v1);
                g_vt[vb + (size_t)hh * TT + t + 8]       = __float2half_rn(v2);
                g_vt[vb + (size_t)(hh + 1) * TT + t + 8] = __float2half_rn(v3);
            }
        }
    }
}

// ---------------------------------------------------------------------------
// Split-K flash attention partial, fp16 m16n8k16, ldmatrix + cp.async pipe.
// exp2-domain softmax with ex2.approx.f16x2; row-sum via ones-MMA.
// CTA = 256 thr (8 warps), Q tile 128 rows; warp w owns rows 16w..16w+15.
// ---------------------------------------------------------------------------
#define QB 0
#define KB 18432
#define KBUF 9216
#define VB 36864
#define ATTN_SMEM 55296

__global__ __launch_bounds__(256) void attn_partial()
{
    const int ch = blockIdx.x, qt = blockIdx.y, b = blockIdx.z;
    const int nkt = 2 * qt + 2;
    if (ch * CH >= nkt) return;

    extern __shared__ __half sma[];
    uint32_t sbase;
    asm("{ .reg .u64 t; cvta.to.shared.u64 t, %1; cvt.u32.u64 %0, t; }"
        : "=r"(sbase) : "l"(sma));

    const int tid = threadIdx.x;
    const int w = tid >> 5;
    const int lane = tid & 31;
    const int r = lane >> 2;
    const int c = lane & 3;
    const int rowA = 16 * w + r;
    const int q0 = qt * 128;
    const size_t base = (size_t)b * TT * HH;
    const size_t vbase = (size_t)b * HH * TT;
    const int unit = (b * 32 + qt) * 8 + ch;

    const uint32_t qa_lane = sbase + QB
        + (16 * w + (lane & 7) + ((lane >> 3) & 1) * 8) * 144
        + ((lane >> 4) & 1) * 16;
    const uint32_t b_lane =
        ((lane & 7) + ((lane >> 4) & 1) * 8) * 144 + ((lane >> 3) & 1) * 16;

    for (int i = tid; i < 128 * 8; i += 256) {
        int row = i >> 3, seg = i & 7;
        *(uint4*)((char*)sma + QB + row * 144 + seg * 16) =
            *(const uint4*)&g_qh[base + (size_t)(q0 + row) * HH + seg * 8];
    }

    const int kt_start = ch * CH;
    const int kt_end = min(kt_start + CH, nkt);

    auto issue = [&](int kt, int buf) {
        const int k0 = kt * 64;
        for (int i = tid; i < 512; i += 256) {
            int row = i >> 3, seg = i & 7;
            cp16(sbase + KB + buf * KBUF + row * 144 + seg * 16,
                 &g_kh[base + (size_t)(k0 + row) * HH + seg * 8]);
            cp16(sbase + VB + buf * KBUF + row * 144 + seg * 16,
                 &g_vt[vbase + (size_t)row * TT + k0 + seg * 8]);
        }
    };

    issue(kt_start, kt_start & 1);
    CP_COMMIT();

    float mA = -1e30f, mB = -1e30f, lA = 0.f, lB = 0.f;
    float o[8][4];
#pragma unroll
    for (int nf = 0; nf < 8; nf++)
#pragma unroll
        for (int j = 0; j < 4; j++) o[nf][j] = 0.f;

    for (int kt = kt_start; kt < kt_end; kt++) {
        const uint32_t kbuf = sbase + KB + (uint32_t)(kt & 1) * KBUF;
        const uint32_t vbuf = sbase + VB + (uint32_t)(kt & 1) * KBUF;
        CP_WAIT0();
        __syncthreads();
        if (kt + 1 < kt_end) {
            issue(kt + 1, (kt + 1) & 1);
            CP_COMMIT();
        }

        // S = Q K^T  (log2-domain logits)
        float s[8][4];
#pragma unroll
        for (int nf = 0; nf < 8; nf++)
#pragma unroll
            for (int j = 0; j < 4; j++) s[nf][j] = 0.f;
#pragma unroll
        for (int kk = 0; kk < 4; kk++) {
            uint32_t a[4];
            ldsm4(a[0], a[1], a[2], a[3], qa_lane + kk * 32);
#pragma unroll
            for (int nfp = 0; nfp < 4; nfp++) {
                uint32_t b0, b1, b2, b3;
                ldsm4(b0, b1, b2, b3,
                      kbuf + b_lane + (uint32_t)(nfp * 2304 + kk * 32));
                mma_f16(s[2 * nfp], a, b0, b1);
                mma_f16(s[2 * nfp + 1], a, b2, b3);
            }
        }

        if (kt >= nkt - 2) {
            int gA = q0 + rowA;
            int k0 = kt * 64;
#pragma unroll
            for (int nf = 0; nf < 8; nf++) {
                int col = k0 + nf * 8 + 2 * c;
                if (col > gA)     s[nf][0] = -1e30f;
                if (col + 1 > gA) s[nf][1] = -1e30f;
                if (col > gA + 8)     s[nf][2] = -1e30f;
                if (col + 1 > gA + 8) s[nf][3] = -1e30f;
            }
        }

        // row max (rows rowA / rowA+8); reduce over 4 c-lanes
        float xA = -1e30f, xB = -1e30f;
#pragma unroll
        for (int nf = 0; nf < 8; nf++) {
            xA = fmaxf(xA, fmaxf(s[nf][0], s[nf][1]));
            xB = fmaxf(xB, fmaxf(s[nf][2], s[nf][3]));
        }
#pragma unroll
        for (int d = 1; d < 4; d <<= 1) {
            xA = fmaxf(xA, __shfl_xor_sync(0xffffffffu, xA, d));
            xB = fmaxf(xB, __shfl_xor_sync(0xffffffffu, xB, d));
        }
        float mnA = fmaxf(mA, xA), mnB = fmaxf(mB, xB);
        float aA = exp2f(mA - mnA), aB = exp2f(mB - mnB);

        // packed fp16 exp2 -> P fragments (no smem, no separate pack)
        uint32_t pp[8][2];
#pragma unroll
        for (int nf = 0; nf < 8; nf++) {
            pp[nf][0] = exp2h2(s[nf][0] - mnA, s[nf][1] - mnA);
            pp[nf][1] = exp2h2(s[nf][2] - mnB, s[nf][3] - mnB);
        }
        mA = mnA;
        mB = mnB;
#pragma unroll
        for (int nf = 0; nf < 8; nf++) {
            o[nf][0] *= aA; o[nf][1] *= aA;
            o[nf][2] *= aB; o[nf][3] *= aB;
        }

        // O += P V; row-sum l via ones-MMA (constant B fragment, no ldsm)
        float sl[4] = {0.f, 0.f, 0.f, 0.f};
#pragma unroll
        for (int kk = 0; kk < 4; kk++) {
            uint32_t a[4] = { pp[2 * kk][0], pp[2 * kk][1],
                              pp[2 * kk + 1][0], pp[2 * kk + 1][1] };
            mma_f16(sl, a, ONES_H2, ONES_H2);
#pragma unroll
            for (int nfp = 0; nfp < 4; nfp++) {
                uint32_t b0, b1, b2, b3;
                ldsm4(b0, b1, b2, b3,
                      vbuf + b_lane + (uint32_t)(nfp * 2304 + kk * 32));
                mma_f16(o[2 * nfp], a, b0, b1);
                mma_f16(o[2 * nfp + 1], a, b2, b3);
            }
        }
        lA = lA * aA + sl[0];   // all cols of ones-MMA hold the row sum
        lB = lB * aB + sl[2];
    }

    // write partial O (unnormalized, fp16) + per-row m, l (fp32)
    __half2* op = (__half2*)g_opart;
#pragma unroll
    for (int nf = 0; nf < 8; nf++) {
        int colo = nf * 8 + 2 * c;
        op[((size_t)unit * 8192 + rowA * 64 + colo) >> 1] =
            __floats2half2_rn(o[nf][0], o[nf][1]);
        op[((size_t)unit * 8192 + (rowA + 8) * 64 + colo) >> 1] =
            __floats2half2_rn(o[nf][2], o[nf][3]);
    }
    if (c == 0) {
        g_mpart[unit * 128 + rowA] = mA;
        g_mpart[unit * 128 + rowA + 8] = mB;
        g_lpart[unit * 128 + rowA] = lA;
        g_lpart[unit * 128 + rowA + 8] = lB;
    }
}

// ---------------------------------------------------------------------------
// Combine: LSE-merge (log2 domain), MLP-batched loads of <=8 fp16 partials.
// grid (32, BB, 4): z = row quarter. 256 thr: row = rq*32 + tid>>3, 8 cols each.
// ---------------------------------------------------------------------------
__global__ __launch_bounds__(256) void attn_combine(float* __restrict__ out)
{
    const int qt = blockIdx.x, b = blockIdx.y, rq = blockIdx.z;
    const int tid = threadIdx.x;
    const int row = rq * 32 + (tid >> 3);
    const int co = (tid & 7) * 8;
    const int nch = (2 * qt + 2 + CH - 1) / CH;
    const int ubase = (b * 32 + qt) * 8;

    float mv[8], lv[8];
#pragma unroll
    for (int i = 0; i < 8; i++) {
        mv[i] = (i < nch) ? g_mpart[(ubase + i) * 128 + row] : -1e30f;
        lv[i] = (i < nch) ? g_lpart[(ubase + i) * 128 + row] : 0.f;
    }
    uint4 raws[8];
#pragma unroll
    for (int i = 0; i < 8; i++) {
        if (i < nch)
            raws[i] = *(const uint4*)
                &g_opart[(size_t)(ubase + i) * 8192 + row * 64 + co];
    }

    float M = -1e30f;
#pragma unroll
    for (int i = 0; i < 8; i++) M = fmaxf(M, mv[i]);

    float L = 0.f;
    float acc[8];
#pragma unroll
    for (int j = 0; j < 8; j++) acc[j] = 0.f;

#pragma unroll
    for (int i = 0; i < 8; i++) {
        if (i >= nch) break;
        float coef = exp2f(mv[i] - M);
        L += coef * lv[i];
        __half2 h0 = *(__half2*)&raws[i].x;
        __half2 h1 = *(__half2*)&raws[i].y;
        __half2 h2 = *(__half2*)&raws[i].z;
        __half2 h3 = *(__half2*)&raws[i].w;
        float2 f0 = __half22float2(h0), f1 = __half22float2(h1);
        float2 f2 = __half22float2(h2), f3 = __half22float2(h3);
        acc[0] += coef * f0.x; acc[1] += coef * f0.y;
        acc[2] += coef * f1.x; acc[3] += coef * f1.y;
        acc[4] += coef * f2.x; acc[5] += coef * f2.y;
        acc[6] += coef * f3.x; acc[7] += coef * f3.y;
    }

    float inv = 1.f / L;
    float* dst = &out[(size_t)b * TT * HH + (size_t)(qt * 128 + row) * HH + co];
#pragma unroll
    for (int j = 0; j < 2; j++) {
        float4 v = make_float4(acc[4 * j] * inv, acc[4 * j + 1] * inv,
                               acc[4 * j + 2] * inv, acc[4 * j + 3] * inv);
        *(float4*)&dst[4 * j] = v;
    }
}

// ---------------------------------------------------------------------------
extern "C" void kernel_launch(void* const* d_in, const int* in_sizes, int n_in,
                              void* d_out, int out_size)
{
    const float* x  = (const float*)d_in[0];
    const float* Wk = (const float*)d_in[1];
    const float* Wq = (const float*)d_in[2];
    const float* Wv = (const float*)d_in[3];
    float* out = (float*)d_out;

    cudaFuncSetAttribute(proj_mma, cudaFuncAttributeMaxDynamicSharedMemorySize, PSMEM);
    cudaFuncSetAttribute(attn_partial, cudaFuncAttributeMaxDynamicSharedMemorySize, ATTN_SMEM);

    wsplit_kernel<<<384, 256>>>(Wk, Wq, Wv);
    proj_mma<<<256, 256, PSMEM>>>(x);
    attn_partial<<<dim3(8, 32, BB), 256, ATTN_SMEM>>>();
    attn_combine<<<dim3(32, BB, 4), 256>>>(out);
}